// round 6
// baseline (speedup 1.0000x reference)
#include <cuda_runtime.h>

// Problem constants (fixed shapes from reference):
//   B=4, S=64, F=64, V=16384, E=512, rows = B*S*F = 16384
#define V_DIM 16384
#define E_DIM 512
#define NROWS 16384
#define TPB    64               // 64-thread blocks -> 32 CTAs/SM resident
#define CHUNKF2 64              // float2 per chunk (= TPB)
#define NCHUNK (V_DIM / (CHUNKF2 * 2))   // 128 chunks of 128 elements
#define DEPTH  4                // deferred-check pipeline depth (128 % 4 == 0)

// Block-per-row scan with a depth-4 deferred check:
//   iteration c issues the load for chunk c+4 and CHECKS chunk c (loaded 4
//   iterations ago, via round-robin buf[c%4] -- compile-time index, no reg
//   copies). The block therefore always keeps 4 chunks (2KB) in flight and
//   never drains at a barrier; 32 blocks/SM -> 64KB/SM sustained in-flight,
//   enough to cover full DRAM latency at peak BW.
// Over-read: E[consumed chunks] ~ 64.5, +4 in flight -> ~53.5% of x.
// Phase B: out[row,:] = W[:,idx] + pos_emb[s,:] + fmap_emb[f,:]; W gathered
// column-wise (4B/32B amplification absorbed by L2; x is __ldcs evict-first,
// out is __stcs, so W stays L2-resident).
__global__ void __launch_bounds__(TPB, 32) combined_embedding_kernel(
    const float* __restrict__ x,
    const float* __restrict__ W,
    const float* __restrict__ pos_emb,
    const float* __restrict__ fmap_emb,
    float* __restrict__ out)
{
    const int row = blockIdx.x;
    const int t = threadIdx.x;

    __shared__ int s_idx;
    if (t == 0) s_idx = -1;
    __syncthreads();

    const float2* xr = reinterpret_cast<const float2*>(x + (size_t)row * V_DIM);

    // Prologue: chunks 0..3 in flight.
    float2 buf[DEPTH];
    #pragma unroll
    for (int d = 0; d < DEPTH; d++)
        buf[d] = __ldcs(&xr[d * CHUNKF2 + t]);

    int idx = 0;

    #pragma unroll 1
    for (int cc = 0; cc < NCHUNK; cc += DEPTH) {
        #pragma unroll
        for (int d = 0; d < DEPTH; d++) {
            const int c = cc + d;
            // Consume chunk c (loaded DEPTH iterations ago).
            float2 v = buf[d];
            // Refill the slot with chunk c+DEPTH (issued before the check waits).
            if (c + DEPTH < NCHUNK)
                buf[d] = __ldcs(&xr[(c + DEPTH) * CHUNKF2 + t]);

            const int base = (c * CHUNKF2 + t) * 2;
            if (v.x != 0.0f) s_idx = base;         // at most one thread per row
            if (v.y != 0.0f) s_idx = base + 1;

            __syncthreads();                       // writes of chunk c visible
            const bool done = (s_idx >= 0);
            __syncthreads();                       // all read before next write
            if (done) goto scan_done;
        }
    }
scan_done:
    idx = (s_idx >= 0) ? s_idx : 0;

    {
        const int s  = (row >> 6) & 63;            // row = ((b*64)+s)*64 + f
        const int fm = row & 63;

        const float4* pe = reinterpret_cast<const float4*>(pos_emb  + (size_t)s  * E_DIM);
        const float4* fe = reinterpret_cast<const float4*>(fmap_emb + (size_t)fm * E_DIM);
        float4* o = reinterpret_cast<float4*>(out + (size_t)row * E_DIM);

        // E=512 -> 128 float4; 64 threads x 2. W gather: column idx, stride V.
        #pragma unroll
        for (int j = 0; j < 2; j++) {
            const int q = j * TPB + t;             // float4 index in the row
            const int e = q * 4;
            float4 p = __ldg(&pe[q]);
            float4 g = __ldg(&fe[q]);
            float4 r;
            r.x = __ldg(&W[(size_t)(e + 0) * V_DIM + idx]) + p.x + g.x;
            r.y = __ldg(&W[(size_t)(e + 1) * V_DIM + idx]) + p.y + g.y;
            r.z = __ldg(&W[(size_t)(e + 2) * V_DIM + idx]) + p.z + g.z;
            r.w = __ldg(&W[(size_t)(e + 3) * V_DIM + idx]) + p.w + g.w;
            __stcs(&o[q], r);                      // streaming: protect W in L2
        }
    }
}

extern "C" void kernel_launch(void* const* d_in, const int* in_sizes, int n_in,
                              void* d_out, int out_size) {
    const float* x        = (const float*)d_in[0];  // [4,64,64,16384]
    const float* W        = (const float*)d_in[1];  // [512,16384]
    const float* pos_emb  = (const float*)d_in[2];  // [256,512]
    const float* fmap_emb = (const float*)d_in[3];  // [256,512]
    float* out = (float*)d_out;                     // [4,64,64,512]

    (void)in_sizes; (void)n_in; (void)out_size;

    combined_embedding_kernel<<<NROWS, TPB>>>(x, W, pos_emb, fmap_emb, out);
}

// round 7
// speedup vs baseline: 1.0513x; 1.0513x over previous
#include <cuda_runtime.h>

// Problem constants (fixed shapes from reference):
//   B=4, S=64, F=64, V=16384, E=512, rows = B*S*F = 16384
#define V_DIM 16384
#define E_DIM 512
#define NROWS 16384
#define TPB   256
#define WPB   (TPB / 32)          // 8 warps (rows) per block
#define CF2   32                  // float2 per chunk per warp (1 per lane)
#define NCHUNK (V_DIM / 64)       // 256 chunks of 64 elements
#define DEPTH  8                  // deferred-check depth (NCHUNK % DEPTH == 0)

// Warp-per-row scan, depth-8 round-robin deferred check, zero barriers.
//   Iteration c: consume buf[d] (chunk c, loaded 8 iterations ago), refill
//   buf[d] with chunk c+8. buf[] is indexed by the compile-time unroll var,
//   so there are NO register copies -- each slot's scoreboard covers a full
//   8-iteration window (2KB always in flight per warp; ~50 warps/SM ->
//   ~100KB/SM, above the ~77KB needed to sustain peak DRAM BW).
//   (R3 failed because its c0=c1 copy chain collapsed the depth to ~1;
//    R6 proved the deferred-check law: T_iter = L/D.)
// Over-read: ~50.2% consumed + 3.1% issued-ahead = ~53.3% of x.
// Phase B: out[row,:] = W[:,idx] + pos_emb[s,:] + fmap_emb[f,:]; W gathered
// column-wise (sector amplification absorbed by L2; x is __ldcs evict-first,
// out is __stcs, so W stays L2-resident).
__global__ void __launch_bounds__(TPB) combined_embedding_kernel(
    const float* __restrict__ x,
    const float* __restrict__ W,
    const float* __restrict__ pos_emb,
    const float* __restrict__ fmap_emb,
    float* __restrict__ out)
{
    const int warp = threadIdx.x >> 5;
    const int lane = threadIdx.x & 31;
    const int row  = blockIdx.x * WPB + warp;

    const float2* xr = reinterpret_cast<const float2*>(x + (size_t)row * V_DIM);

    // Prologue: chunks 0..7 in flight.
    float2 buf[DEPTH];
    #pragma unroll
    for (int d = 0; d < DEPTH; d++)
        buf[d] = __ldcs(&xr[d * CF2 + lane]);

    int idx = -1;

    #pragma unroll 1
    for (int cc = 0; cc < NCHUNK; cc += DEPTH) {
        #pragma unroll
        for (int d = 0; d < DEPTH; d++) {
            const int c = cc + d;
            float2 v = buf[d];                       // chunk c (issued 8 iters ago)
            if (c + DEPTH < NCHUNK)                  // refill slot with chunk c+8
                buf[d] = __ldcs(&xr[(c + DEPTH) * CF2 + lane]);

            const bool nz = (v.x != 0.0f) | (v.y != 0.0f);
            const unsigned m = __ballot_sync(0xffffffffu, nz);
            if (m) {
                const int src  = __ffs(m) - 1;
                const int cand = c * 64 + lane * 2 + (v.x != 0.0f ? 0 : 1);
                idx = __shfl_sync(0xffffffffu, cand, src);
                goto scan_done;
            }
        }
    }
scan_done:
    if (idx < 0) idx = 0;

    // ---- Phase B: gather + add, warp-wide ----
    {
        const int s  = (row >> 6) & 63;              // row = ((b*64)+s)*64 + f
        const int fm = row & 63;

        const float4* pe = reinterpret_cast<const float4*>(pos_emb  + (size_t)s  * E_DIM);
        const float4* fe = reinterpret_cast<const float4*>(fmap_emb + (size_t)fm * E_DIM);
        float4* o = reinterpret_cast<float4*>(out + (size_t)row * E_DIM);

        // E=512 -> 128 float4; 32 lanes x 4. W gather: column idx, stride V.
        #pragma unroll
        for (int j = 0; j < 4; j++) {
            const int q = j * 32 + lane;             // float4 index within row
            const int e = q * 4;
            float4 p = __ldg(&pe[q]);
            float4 g = __ldg(&fe[q]);
            float4 r;
            r.x = __ldg(&W[(size_t)(e + 0) * V_DIM + idx]) + p.x + g.x;
            r.y = __ldg(&W[(size_t)(e + 1) * V_DIM + idx]) + p.y + g.y;
            r.z = __ldg(&W[(size_t)(e + 2) * V_DIM + idx]) + p.z + g.z;
            r.w = __ldg(&W[(size_t)(e + 3) * V_DIM + idx]) + p.w + g.w;
            __stcs(&o[q], r);                        // streaming: protect W in L2
        }
    }
}

extern "C" void kernel_launch(void* const* d_in, const int* in_sizes, int n_in,
                              void* d_out, int out_size) {
    const float* x        = (const float*)d_in[0];  // [4,64,64,16384]
    const float* W        = (const float*)d_in[1];  // [512,16384]
    const float* pos_emb  = (const float*)d_in[2];  // [256,512]
    const float* fmap_emb = (const float*)d_in[3];  // [256,512]
    float* out = (float*)d_out;                     // [4,64,64,512]

    (void)in_sizes; (void)n_in; (void)out_size;

    combined_embedding_kernel<<<NROWS / WPB, TPB>>>(x, W, pos_emb, fmap_emb, out);
}